// round 10
// baseline (speedup 1.0000x reference)
#include <cuda_runtime.h>
#include <cuda_fp16.h>
#include <math.h>
#include <stdint.h>

#define Bb 2
#define Hh 16
#define Nn 2048
#define Dd 128
#define NP 7
#define BH (Bb*Hh)

// ---------------- device scratch ----------------
__device__ int g_qhash[BH*Nn];
__device__ int g_khash[BH*Nn];
__device__ int g_sidx[BH*Nn];
__device__ int g_keep[64];
__device__ __align__(16) unsigned char g_khi[(size_t)BH*Nn*256];
__device__ __align__(16) unsigned char g_klo[(size_t)BH*Nn*256];
__device__ __align__(16) unsigned char g_vhi[(size_t)BH*Nn*256];

// ---------------- helpers ----------------
__device__ __forceinline__ uint32_t smem_u32(const void* p) {
    uint32_t a;
    asm("{ .reg .u64 t; cvta.to.shared.u64 t, %1; cvt.u32.u64 %0, t; }" : "=r"(a) : "l"(p));
    return a;
}
__device__ __forceinline__ uint32_t pack2h(float a, float b) {
    __half2 h = __floats2half2_rn(a, b);
    return *(uint32_t*)&h;
}
__device__ __forceinline__ void split2h(float x0, float x1, uint32_t& hi, uint32_t& lo) {
    __half h0 = __float2half_rn(x0), h1 = __float2half_rn(x1);
    float r0 = x0 - __half2float(h0), r1 = x1 - __half2float(h1);
    hi = pack2h(__half2float(h0), __half2float(h1));
    lo = pack2h(r0, r1);
}
__device__ __forceinline__ void mma(float d[4], const uint32_t a[4], uint32_t b0, uint32_t b1) {
    asm volatile("mma.sync.aligned.m16n8k16.row.col.f32.f16.f16.f32 "
        "{%0,%1,%2,%3},{%4,%5,%6,%7},{%8,%9},{%0,%1,%2,%3};"
        : "+f"(d[0]), "+f"(d[1]), "+f"(d[2]), "+f"(d[3])
        : "r"(a[0]), "r"(a[1]), "r"(a[2]), "r"(a[3]), "r"(b0), "r"(b1));
}
__device__ __forceinline__ void ldsm4(uint32_t r[4], uint32_t a) {
    asm volatile("ldmatrix.sync.aligned.m8n8.x4.shared.b16 {%0,%1,%2,%3},[%4];"
        : "=r"(r[0]), "=r"(r[1]), "=r"(r[2]), "=r"(r[3]) : "r"(a));
}
__device__ __forceinline__ void ldsm4t(uint32_t r[4], uint32_t a) {
    asm volatile("ldmatrix.sync.aligned.m8n8.x4.trans.shared.b16 {%0,%1,%2,%3},[%4];"
        : "=r"(r[0]), "=r"(r[1]), "=r"(r[2]), "=r"(r[3]) : "r"(a));
}
#define CPA(dst, src) asm volatile("cp.async.cg.shared.global [%0],[%1],16;" :: "r"(dst), "l"(src))
#define CPC()  asm volatile("cp.async.commit_group;" ::: "memory")
#define CPW(n) asm volatile("cp.async.wait_group %0;" :: "n"(n) : "memory")

// ---------------- LSH hash (also zero-inits g_keep) ----------------
__global__ void hash_kernel(const float* __restrict__ q, const float* __restrict__ k,
                            const float* __restrict__ pd) {
    if (blockIdx.x == 0 && threadIdx.x < 64) g_keep[threadIdx.x] = 0;
    __shared__ float pds[Dd*NP];
    for (int i = threadIdx.x; i < Dd*NP; i += blockDim.x) pds[i] = pd[i];
    __syncthreads();
    int warp = threadIdx.x >> 5, lane = threadIdx.x & 31;
    int gid = blockIdx.x * 8 + warp;
    int t = gid >> 16, row = gid & 65535;
    const float* src = t ? k : q;
    int n = row & (Nn-1), h = (row >> 11) & (Hh-1), b = row >> 15;
    float4 x = ((const float4*)(src + ((size_t)(b*Nn+n)*Hh + h)*Dd))[lane];
    int d0 = lane * 4;
    float acc[NP];
    #pragma unroll
    for (int p = 0; p < NP; p++)
        acc[p] = x.x*pds[(d0+0)*NP+p] + x.y*pds[(d0+1)*NP+p]
               + x.z*pds[(d0+2)*NP+p] + x.w*pds[(d0+3)*NP+p];
    #pragma unroll
    for (int p = 0; p < NP; p++)
        #pragma unroll
        for (int o = 16; o; o >>= 1) acc[p] += __shfl_xor_sync(0xffffffffu, acc[p], o);
    if (lane == 0) {
        int bin = 0;
        #pragma unroll
        for (int p = 0; p < NP; p++) bin |= ((acc[p] > 0.f) ? 1 : 0) << p;
        (t ? g_khash : g_qhash)[row] = bin ^ (bin >> 1);
    }
}

// ---------------- stable counting sort per (b,h) + fused keep ----------------
// keep[j] (j = sorted_pos>>5) |= (qhash_sorted[pos] == khash[pos]) for any bh.
__global__ void sort_kernel() {
    __shared__ int hs[Nn];
    __shared__ int cnt[128];
    __shared__ int ks[64];
    int bh = blockIdx.x, base = bh * Nn;
    for (int i = threadIdx.x; i < Nn; i += 128) hs[i] = g_qhash[base + i];
    if (threadIdx.x < 64) ks[threadIdx.x] = 0;
    __syncthreads();
    int key = threadIdx.x, c = 0;
    for (int i = 0; i < Nn; i++) c += (hs[i] == key);
    cnt[key] = c;
    __syncthreads();
    int off = 0;
    for (int j = 0; j < key; j++) off += cnt[j];
    for (int i = 0; i < Nn; i++)
        if (hs[i] == key) {
            g_sidx[base + off] = i;
            if (key == g_khash[base + off]) ks[off >> 5] = 1;
            off++;
        }
    __syncthreads();
    if (threadIdx.x < 64 && ks[threadIdx.x]) atomicOr(&g_keep[threadIdx.x], 1);
}

// ---------------- K/V prep ----------------
// K: fp16 hi/lo split (keep-zeroed); V: single fp16. Row images 256B,
// 16B chunk c stored at (c ^ (n&7)).
__global__ void kvprep(const float* __restrict__ kg, const float* __restrict__ vg) {
    int idx = blockIdx.x * 256 + threadIdx.x;        // 2*BH*Nn*16
    int c = idx & 15;
    int row = (idx >> 4) & (Nn-1);
    int bh  = (idx >> 15) & (BH-1);
    int isv = idx >> 20;
    int h = bh & 15, b = bh >> 4;
    const float* src = isv ? vg : kg;
    const float4* sp = (const float4*)(src + ((size_t)(b*Nn+row)*Hh + h)*Dd) + c*2;
    float4 x0 = sp[0], x1 = sp[1];
    size_t off = ((size_t)(bh*Nn + row))*256 + (size_t)((c ^ (row&7)) << 4);
    if (isv) {
        uint4 hv;
        hv.x = pack2h(x0.x, x0.y); hv.y = pack2h(x0.z, x0.w);
        hv.z = pack2h(x1.x, x1.y); hv.w = pack2h(x1.z, x1.w);
        *(uint4*)(g_vhi + off) = hv;
    } else {
        float kp = g_keep[h*4 + (row >> 9)] ? 1.f : 0.f;
        uint4 hv, lv;
        split2h(x0.x*kp, x0.y*kp, hv.x, lv.x);
        split2h(x0.z*kp, x0.w*kp, hv.y, lv.y);
        split2h(x1.x*kp, x1.y*kp, hv.z, lv.z);
        split2h(x1.z*kp, x1.w*kp, hv.w, lv.w);
        *(uint4*)(g_khi + off) = hv;
        *(uint4*)(g_klo + off) = lv;
    }
}

// ---------------- HMMA flash attention ----------------
// fp16. S = Qhi*Khi + Qlo*Khi + Qhi*Klo (Q pre-scaled by D^-0.5);
// PV = P*V, single fp16 P. p = exp(s), no shift (P fp16-normal).
// Pipelined inner iter: S(sub0), S(sub1), then per-sub exp/pack/PV so
// MUFU-exp overlaps the HMMA streams. 2-stage cp.async over 128-key tiles.
#define STAGE   98304           /* KHI 32K | KLO 32K | V 32K */
#define OFF_KLO 32768
#define OFF_V   65536
#define SMEMT   196608

__global__ void __launch_bounds__(256, 1)
attn_kernel(const float* __restrict__ qg, float* __restrict__ out) {
    extern __shared__ __align__(16) unsigned char dsm[];
    uint32_t sb = smem_u32(dsm);
    int tid = threadIdx.x, warp = tid >> 5, lane = tid & 31;
    int qt = 15 - (int)blockIdx.x, h = blockIdx.y, b = blockIdx.z;
    int bh = b*Hh + h;

    // ---- stage Q (gathered rows, pre-scaled, fp16 hi/lo split)
    {
        const float sc = 0.0883883476483184f;   // 128^-0.5
        #pragma unroll
        for (int it = 0; it < 8; it++) {
            int i = tid + it*256;
            int row = i >> 4, c = i & 15;
            int n = g_sidx[bh*Nn + qt*128 + row];
            const float4* qp = (const float4*)(qg + ((size_t)(b*Nn+n)*Hh + h)*Dd) + c*2;
            float4 x0 = qp[0], x1 = qp[1];
            uint4 hv, lv;
            split2h(x0.x*sc, x0.y*sc, hv.x, lv.x);
            split2h(x0.z*sc, x0.w*sc, hv.y, lv.y);
            split2h(x1.x*sc, x1.y*sc, hv.z, lv.z);
            split2h(x1.z*sc, x1.w*sc, hv.w, lv.w);
            uint32_t off = row*256 + ((c ^ (row&7)) << 4);
            *(uint4*)(dsm + off) = hv;
            *(uint4*)(dsm + 32768 + off) = lv;
        }
    }
    __syncthreads();

    // ---- extract Q fragments (A operand, 8 k-steps)
    uint32_t qh[8][4], ql[8][4];
    {
        int qrow = 16*warp + (lane & 15);
        int cbit = lane >> 4, rsw = qrow & 7;
        uint32_t qb = sb + qrow*256;
        #pragma unroll
        for (int kk = 0; kk < 8; kk++) {
            uint32_t a = qb + (((2*kk + cbit) ^ rsw) << 4);
            ldsm4(qh[kk], a);
            ldsm4(ql[kk], a + 32768);
        }
    }
    __syncthreads();

    size_t gbase = (size_t)(bh*Nn) * 256;

    // ---- prologue: stage 0 <- key tile 0 (128 keys, 32KB per image)
    #pragma unroll
    for (int i2 = 0; i2 < 8; i2++) {
        int i = tid + i2*256;
        CPA(sb + i*16,           g_khi + gbase + i*16);
        CPA(sb + OFF_KLO + i*16, g_klo + gbase + i*16);
        CPA(sb + OFF_V + i*16,   g_vhi + gbase + i*16);
    }
    CPC();

    float o[16][4];
    #pragma unroll
    for (int j = 0; j < 16; j++)
        #pragma unroll
        for (int e = 0; e < 4; e++) o[j][e] = 0.f;
    float lA = 0.f, lB = 0.f;

    int keyl = lane & 15, ksw = keyl & 7, cbit = lane >> 4;
    int grA = qt*128 + 16*warp + (lane >> 2), grB = grA + 8;

    for (int kt = 0; kt <= qt; kt++) {
        CPW(0);
        __syncthreads();

        // prefetch next 128-key tile into the other stage
        if (kt < qt) {
            uint32_t st = sb + ((kt+1)&1)*STAGE;
            size_t gs = gbase + (size_t)(kt+1)*32768;
            #pragma unroll
            for (int i2 = 0; i2 < 8; i2++) {
                int i = tid + i2*256;
                CPA(st + i*16,           g_khi + gs + i*16);
                CPA(st + OFF_KLO + i*16, g_klo + gs + i*16);
                CPA(st + OFF_V + i*16,   g_vhi + gs + i*16);
            }
            CPC();
        }

        bool dg = (kt == qt);
        uint32_t stage = sb + (kt&1)*STAGE;

        // ---- S phase: both 64-key sub-blocks
        float s[2][8][4];
        #pragma unroll
        for (int sub = 0; sub < 2; sub++) {
            uint32_t stK = stage + sub*16384 + keyl*256;
            #pragma unroll
            for (int j = 0; j < 8; j++)
                #pragma unroll
                for (int e = 0; e < 4; e++) s[sub][j][e] = 0.f;
            #pragma unroll
            for (int kk = 0; kk < 8; kk++) {
                #pragma unroll
                for (int jp = 0; jp < 4; jp++) {
                    uint32_t kb[4], kb2[4];
                    uint32_t a = stK + jp*4096 + (((2*kk + cbit) ^ ksw) << 4);
                    ldsm4(kb, a);
                    ldsm4(kb2, a + OFF_KLO);
                    mma(s[sub][2*jp],   qh[kk], kb[0], kb[2]);
                    mma(s[sub][2*jp+1], qh[kk], kb[1], kb[3]);
                    mma(s[sub][2*jp],   ql[kk], kb[0], kb[2]);
                    mma(s[sub][2*jp+1], ql[kk], kb[1], kb[3]);
                    mma(s[sub][2*jp],   qh[kk], kb2[0], kb2[2]);
                    mma(s[sub][2*jp+1], qh[kk], kb2[1], kb2[3]);
                }
            }
        }

        // ---- per sub: exp -> pack -> PV (exp overlaps other sub's HMMA)
        #pragma unroll
        for (int sub = 0; sub < 2; sub++) {
            uint32_t stV = stage + OFF_V + sub*16384 + keyl*256;
            float p[8][4];
            #pragma unroll
            for (int j = 0; j < 8; j++) {
                int gc = kt*128 + sub*64 + 8*j + 2*(lane & 3);
                float p0 = __expf(s[sub][j][0]);
                float p1 = __expf(s[sub][j][1]);
                float p2 = __expf(s[sub][j][2]);
                float p3 = __expf(s[sub][j][3]);
                if (dg) {
                    if (gc     > grA) p0 = 0.f;
                    if (gc + 1 > grA) p1 = 0.f;
                    if (gc     > grB) p2 = 0.f;
                    if (gc + 1 > grB) p3 = 0.f;
                }
                lA += p0 + p1;
                lB += p2 + p3;
                p[j][0] = p0; p[j][1] = p1; p[j][2] = p2; p[j][3] = p3;
            }

            uint32_t phi[4][4];
            #pragma unroll
            for (int k2 = 0; k2 < 4; k2++) {
                #pragma unroll
                for (int u = 0; u < 4; u++) {
                    int j = 2*k2 + (u >> 1);
                    phi[k2][u] = pack2h(p[j][(u & 1) ? 2 : 0], p[j][(u & 1) ? 3 : 1]);
                }
            }

            #pragma unroll
            for (int k2 = 0; k2 < 4; k2++) {
                #pragma unroll
                for (int jp = 0; jp < 8; jp++) {
                    uint32_t vb[4];
                    uint32_t a = stV + k2*4096 + (((2*jp + cbit) ^ ksw) << 4);
                    ldsm4t(vb, a);
                    mma(o[2*jp],   phi[k2], vb[0], vb[1]);
                    mma(o[2*jp+1], phi[k2], vb[2], vb[3]);
                }
            }
        }
    }

    // ---- epilogue: reduce l, normalize, scatter to original rows
    #pragma unroll
    for (int ox = 1; ox < 4; ox <<= 1) {
        lA += __shfl_xor_sync(0xffffffffu, lA, ox);
        lB += __shfl_xor_sync(0xffffffffu, lB, ox);
    }
    float iA = 1.f / lA, iB = 1.f / lB;
    int nA = g_sidx[bh*Nn + qt*128 + 16*warp + (lane >> 2)];
    int nB = g_sidx[bh*Nn + qt*128 + 16*warp + (lane >> 2) + 8];
    float* opA = out + ((size_t)(b*Nn+nA)*Hh + h)*Dd;
    float* opB = out + ((size_t)(b*Nn+nB)*Hh + h)*Dd;
    #pragma unroll
    for (int j = 0; j < 16; j++) {
        int col = 8*j + 2*(lane & 3);
        *(float2*)(opA + col) = make_float2(o[j][0]*iA, o[j][1]*iA);
        *(float2*)(opB + col) = make_float2(o[j][2]*iB, o[j][3]*iB);
    }
}

// ---------------- launch ----------------
extern "C" void kernel_launch(void* const* d_in, const int* in_sizes, int n_in,
                              void* d_out, int out_size) {
    const float* q  = (const float*)d_in[0];
    const float* k  = (const float*)d_in[1];
    const float* v  = (const float*)d_in[2];
    const float* pd = (const float*)d_in[3];
    float* out = (float*)d_out;

    hash_kernel<<<16384, 256>>>(q, k, pd);
    sort_kernel<<<BH, 128>>>();
    kvprep<<<8192, 256>>>(k, v);
    cudaFuncSetAttribute(attn_kernel, cudaFuncAttributeMaxDynamicSharedMemorySize, SMEMT);
    attn_kernel<<<dim3(16, Hh, Bb), 256, SMEMT>>>(q, out);
}

// round 11
// speedup vs baseline: 1.0404x; 1.0404x over previous
#include <cuda_runtime.h>
#include <cuda_fp16.h>
#include <math.h>
#include <stdint.h>

#define Bb 2
#define Hh 16
#define Nn 2048
#define Dd 128
#define NP 7
#define BH (Bb*Hh)

// ---------------- device scratch ----------------
__device__ int g_qhash[BH*Nn];
__device__ int g_khash[BH*Nn];
__device__ int g_sidx[BH*Nn];
__device__ int g_keep[64];
__device__ __align__(16) unsigned char g_khi[(size_t)BH*Nn*256];
__device__ __align__(16) unsigned char g_klo[(size_t)BH*Nn*256];
__device__ __align__(16) unsigned char g_vhi[(size_t)BH*Nn*256];

// ---------------- helpers ----------------
__device__ __forceinline__ uint32_t smem_u32(const void* p) {
    uint32_t a;
    asm("{ .reg .u64 t; cvta.to.shared.u64 t, %1; cvt.u32.u64 %0, t; }" : "=r"(a) : "l"(p));
    return a;
}
__device__ __forceinline__ uint32_t pack2h(float a, float b) {
    __half2 h = __floats2half2_rn(a, b);
    return *(uint32_t*)&h;
}
__device__ __forceinline__ void split2h(float x0, float x1, uint32_t& hi, uint32_t& lo) {
    __half h0 = __float2half_rn(x0), h1 = __float2half_rn(x1);
    float r0 = x0 - __half2float(h0), r1 = x1 - __half2float(h1);
    hi = pack2h(__half2float(h0), __half2float(h1));
    lo = pack2h(r0, r1);
}
__device__ __forceinline__ void mma(float d[4], const uint32_t a[4], uint32_t b0, uint32_t b1) {
    asm volatile("mma.sync.aligned.m16n8k16.row.col.f32.f16.f16.f32 "
        "{%0,%1,%2,%3},{%4,%5,%6,%7},{%8,%9},{%0,%1,%2,%3};"
        : "+f"(d[0]), "+f"(d[1]), "+f"(d[2]), "+f"(d[3])
        : "r"(a[0]), "r"(a[1]), "r"(a[2]), "r"(a[3]), "r"(b0), "r"(b1));
}
__device__ __forceinline__ void ldsm4(uint32_t r[4], uint32_t a) {
    asm volatile("ldmatrix.sync.aligned.m8n8.x4.shared.b16 {%0,%1,%2,%3},[%4];"
        : "=r"(r[0]), "=r"(r[1]), "=r"(r[2]), "=r"(r[3]) : "r"(a));
}
__device__ __forceinline__ void ldsm4t(uint32_t r[4], uint32_t a) {
    asm volatile("ldmatrix.sync.aligned.m8n8.x4.trans.shared.b16 {%0,%1,%2,%3},[%4];"
        : "=r"(r[0]), "=r"(r[1]), "=r"(r[2]), "=r"(r[3]) : "r"(a));
}
#define CPA(dst, src) asm volatile("cp.async.cg.shared.global [%0],[%1],16;" :: "r"(dst), "l"(src))
#define CPC()  asm volatile("cp.async.commit_group;" ::: "memory")
#define CPW(n) asm volatile("cp.async.wait_group %0;" :: "n"(n) : "memory")

// ---------------- LSH hash (also zero-inits g_keep) ----------------
__global__ void hash_kernel(const float* __restrict__ q, const float* __restrict__ k,
                            const float* __restrict__ pd) {
    if (blockIdx.x == 0 && threadIdx.x < 64) g_keep[threadIdx.x] = 0;
    __shared__ float pds[Dd*NP];
    for (int i = threadIdx.x; i < Dd*NP; i += blockDim.x) pds[i] = pd[i];
    __syncthreads();
    int warp = threadIdx.x >> 5, lane = threadIdx.x & 31;
    int gid = blockIdx.x * 8 + warp;
    int t = gid >> 16, row = gid & 65535;
    const float* src = t ? k : q;
    int n = row & (Nn-1), h = (row >> 11) & (Hh-1), b = row >> 15;
    float4 x = ((const float4*)(src + ((size_t)(b*Nn+n)*Hh + h)*Dd))[lane];
    int d0 = lane * 4;
    float acc[NP];
    #pragma unroll
    for (int p = 0; p < NP; p++)
        acc[p] = x.x*pds[(d0+0)*NP+p] + x.y*pds[(d0+1)*NP+p]
               + x.z*pds[(d0+2)*NP+p] + x.w*pds[(d0+3)*NP+p];
    #pragma unroll
    for (int p = 0; p < NP; p++)
        #pragma unroll
        for (int o = 16; o; o >>= 1) acc[p] += __shfl_xor_sync(0xffffffffu, acc[p], o);
    if (lane == 0) {
        int bin = 0;
        #pragma unroll
        for (int p = 0; p < NP; p++) bin |= ((acc[p] > 0.f) ? 1 : 0) << p;
        (t ? g_khash : g_qhash)[row] = bin ^ (bin >> 1);
    }
}

// ---------------- stable counting sort per (b,h) + fused keep ----------------
__global__ void sort_kernel() {
    __shared__ int hs[Nn];
    __shared__ int cnt[128];
    __shared__ int ks[64];
    int bh = blockIdx.x, base = bh * Nn;
    for (int i = threadIdx.x; i < Nn; i += 128) hs[i] = g_qhash[base + i];
    if (threadIdx.x < 64) ks[threadIdx.x] = 0;
    __syncthreads();
    int key = threadIdx.x, c = 0;
    for (int i = 0; i < Nn; i++) c += (hs[i] == key);
    cnt[key] = c;
    __syncthreads();
    int off = 0;
    for (int j = 0; j < key; j++) off += cnt[j];
    for (int i = 0; i < Nn; i++)
        if (hs[i] == key) {
            g_sidx[base + off] = i;
            if (key == g_khash[base + off]) ks[off >> 5] = 1;
            off++;
        }
    __syncthreads();
    if (threadIdx.x < 64 && ks[threadIdx.x]) atomicOr(&g_keep[threadIdx.x], 1);
}

// ---------------- K/V prep ----------------
__global__ void kvprep(const float* __restrict__ kg, const float* __restrict__ vg) {
    int idx = blockIdx.x * 256 + threadIdx.x;        // 2*BH*Nn*16
    int c = idx & 15;
    int row = (idx >> 4) & (Nn-1);
    int bh  = (idx >> 15) & (BH-1);
    int isv = idx >> 20;
    int h = bh & 15, b = bh >> 4;
    const float* src = isv ? vg : kg;
    const float4* sp = (const float4*)(src + ((size_t)(b*Nn+row)*Hh + h)*Dd) + c*2;
    float4 x0 = sp[0], x1 = sp[1];
    size_t off = ((size_t)(bh*Nn + row))*256 + (size_t)((c ^ (row&7)) << 4);
    if (isv) {
        uint4 hv;
        hv.x = pack2h(x0.x, x0.y); hv.y = pack2h(x0.z, x0.w);
        hv.z = pack2h(x1.x, x1.y); hv.w = pack2h(x1.z, x1.w);
        *(uint4*)(g_vhi + off) = hv;
    } else {
        float kp = g_keep[h*4 + (row >> 9)] ? 1.f : 0.f;
        uint4 hv, lv;
        split2h(x0.x*kp, x0.y*kp, hv.x, lv.x);
        split2h(x0.z*kp, x0.w*kp, hv.y, lv.y);
        split2h(x1.x*kp, x1.y*kp, hv.z, lv.z);
        split2h(x1.z*kp, x1.w*kp, hv.w, lv.w);
        *(uint4*)(g_khi + off) = hv;
        *(uint4*)(g_klo + off) = lv;
    }
}

// ---------------- HMMA flash attention: 2 CTAs/SM ----------------
// 128 threads (4 warps), BM=64 Q-rows, 64-key pipeline tiles, 2-stage
// cp.async, 48KB/stage (K|Klo|V 16KB each) -> 96KB smem/CTA -> 2 CTAs/SM.
// fp16: S = Qhi*Khi + Qlo*Khi + Qhi*Klo (Q pre-scaled); PV = P*V, p=exp(s).
#define STAGE   49152
#define OFF_KLO 16384
#define OFF_V   32768
#define SMEMT   98304

__global__ void __launch_bounds__(128, 2)
attn_kernel(const float* __restrict__ qg, float* __restrict__ out) {
    extern __shared__ __align__(16) unsigned char dsm[];
    uint32_t sb = smem_u32(dsm);
    int tid = threadIdx.x, warp = tid >> 5, lane = tid & 31;
    int qt = 31 - (int)blockIdx.x, h = blockIdx.y, b = blockIdx.z;
    int bh = b*Hh + h;

    // ---- stage Q (64 gathered rows, pre-scaled, fp16 hi/lo split)
    {
        const float sc = 0.0883883476483184f;   // 128^-0.5
        #pragma unroll
        for (int it = 0; it < 8; it++) {
            int i = tid + it*128;
            int row = i >> 4, c = i & 15;
            int n = g_sidx[bh*Nn + qt*64 + row];
            const float4* qp = (const float4*)(qg + ((size_t)(b*Nn+n)*Hh + h)*Dd) + c*2;
            float4 x0 = qp[0], x1 = qp[1];
            uint4 hv, lv;
            split2h(x0.x*sc, x0.y*sc, hv.x, lv.x);
            split2h(x0.z*sc, x0.w*sc, hv.y, lv.y);
            split2h(x1.x*sc, x1.y*sc, hv.z, lv.z);
            split2h(x1.z*sc, x1.w*sc, hv.w, lv.w);
            uint32_t off = row*256 + ((c ^ (row&7)) << 4);
            *(uint4*)(dsm + off) = hv;
            *(uint4*)(dsm + 16384 + off) = lv;
        }
    }
    __syncthreads();

    // ---- extract Q fragments (A operand, 8 k-steps)
    uint32_t qh[8][4], ql[8][4];
    {
        int qrow = 16*warp + (lane & 15);
        int cbit = lane >> 4, rsw = qrow & 7;
        uint32_t qb = sb + qrow*256;
        #pragma unroll
        for (int kk = 0; kk < 8; kk++) {
            uint32_t a = qb + (((2*kk + cbit) ^ rsw) << 4);
            ldsm4(qh[kk], a);
            ldsm4(ql[kk], a + 16384);
        }
    }
    __syncthreads();

    size_t gbase = (size_t)(bh*Nn) * 256;

    // ---- prologue: stage 0 <- key tile 0 (64 keys, 16KB per image)
    #pragma unroll
    for (int i2 = 0; i2 < 8; i2++) {
        int i = tid + i2*128;
        CPA(sb + i*16,           g_khi + gbase + i*16);
        CPA(sb + OFF_KLO + i*16, g_klo + gbase + i*16);
        CPA(sb + OFF_V + i*16,   g_vhi + gbase + i*16);
    }
    CPC();

    float o[16][4];
    #pragma unroll
    for (int j = 0; j < 16; j++)
        #pragma unroll
        for (int e = 0; e < 4; e++) o[j][e] = 0.f;
    float lA = 0.f, lB = 0.f;

    int keyl = lane & 15, ksw = keyl & 7, cbit = lane >> 4;
    int grA = qt*64 + 16*warp + (lane >> 2), grB = grA + 8;

    for (int kt = 0; kt <= qt; kt++) {
        CPW(0);
        __syncthreads();

        // prefetch next 64-key tile into the other stage
        if (kt < qt) {
            uint32_t st = sb + ((kt+1)&1)*STAGE;
            size_t gs = gbase + (size_t)(kt+1)*16384;
            #pragma unroll
            for (int i2 = 0; i2 < 8; i2++) {
                int i = tid + i2*128;
                CPA(st + i*16,           g_khi + gs + i*16);
                CPA(st + OFF_KLO + i*16, g_klo + gs + i*16);
                CPA(st + OFF_V + i*16,   g_vhi + gs + i*16);
            }
            CPC();
        }

        bool dg = (kt == qt);
        uint32_t stK = sb + (kt&1)*STAGE + keyl*256;
        uint32_t stV = stK + OFF_V;

        // ---- S = Qhi*Khi + Qlo*Khi + Qhi*Klo  (16x64 per warp)
        float s[8][4];
        #pragma unroll
        for (int j = 0; j < 8; j++)
            #pragma unroll
            for (int e = 0; e < 4; e++) s[j][e] = 0.f;

        #pragma unroll
        for (int kk = 0; kk < 8; kk++) {
            #pragma unroll
            for (int jp = 0; jp < 4; jp++) {
                uint32_t kb[4], kb2[4];
                uint32_t a = stK + jp*4096 + (((2*kk + cbit) ^ ksw) << 4);
                ldsm4(kb, a);
                ldsm4(kb2, a + OFF_KLO);
                mma(s[2*jp],   qh[kk], kb[0], kb[2]);
                mma(s[2*jp+1], qh[kk], kb[1], kb[3]);
                mma(s[2*jp],   ql[kk], kb[0], kb[2]);
                mma(s[2*jp+1], ql[kk], kb[1], kb[3]);
                mma(s[2*jp],   qh[kk], kb2[0], kb2[2]);
                mma(s[2*jp+1], qh[kk], kb2[1], kb2[3]);
            }
        }

        // ---- softmax: p = exp(s), causal mask on diagonal tile
        float p[8][4];
        #pragma unroll
        for (int j = 0; j < 8; j++) {
            int gc = kt*64 + 8*j + 2*(lane & 3);
            float p0 = __expf(s[j][0]);
            float p1 = __expf(s[j][1]);
            float p2 = __expf(s[j][2]);
            float p3 = __expf(s[j][3]);
            if (dg) {
                if (gc     > grA) p0 = 0.f;
                if (gc + 1 > grA) p1 = 0.f;
                if (gc     > grB) p2 = 0.f;
                if (gc + 1 > grB) p3 = 0.f;
            }
            lA += p0 + p1;
            lB += p2 + p3;
            p[j][0] = p0; p[j][1] = p1; p[j][2] = p2; p[j][3] = p3;
        }

        // ---- pack P fragments (single fp16)
        uint32_t phi[4][4];
        #pragma unroll
        for (int k2 = 0; k2 < 4; k2++) {
            #pragma unroll
            for (int u = 0; u < 4; u++) {
                int j = 2*k2 + (u >> 1);
                phi[k2][u] = pack2h(p[j][(u & 1) ? 2 : 0], p[j][(u & 1) ? 3 : 1]);
            }
        }

        // ---- O += P * V
        #pragma unroll
        for (int k2 = 0; k2 < 4; k2++) {
            #pragma unroll
            for (int jp = 0; jp < 8; jp++) {
                uint32_t vb[4];
                uint32_t a = stV + k2*4096 + (((2*jp + cbit) ^ ksw) << 4);
                ldsm4t(vb, a);
                mma(o[2*jp],   phi[k2], vb[0], vb[1]);
                mma(o[2*jp+1], phi[k2], vb[2], vb[3]);
            }
        }
    }

    // ---- epilogue: reduce l, normalize, scatter to original rows
    #pragma unroll
    for (int ox = 1; ox < 4; ox <<= 1) {
        lA += __shfl_xor_sync(0xffffffffu, lA, ox);
        lB += __shfl_xor_sync(0xffffffffu, lB, ox);
    }
    float iA = 1.f / lA, iB = 1.f / lB;
    int nA = g_sidx[bh*Nn + qt*64 + 16*warp + (lane >> 2)];
    int nB = g_sidx[bh*Nn + qt*64 + 16*warp + (lane >> 2) + 8];
    float* opA = out + ((size_t)(b*Nn+nA)*Hh + h)*Dd;
    float* opB = out + ((size_t)(b*Nn+nB)*Hh + h)*Dd;
    #pragma unroll
    for (int j = 0; j < 16; j++) {
        int col = 8*j + 2*(lane & 3);
        *(float2*)(opA + col) = make_float2(o[j][0]*iA, o[j][1]*iA);
        *(float2*)(opB + col) = make_float2(o[j][2]*iB, o[j][3]*iB);
    }
}

// ---------------- launch ----------------
extern "C" void kernel_launch(void* const* d_in, const int* in_sizes, int n_in,
                              void* d_out, int out_size) {
    const float* q  = (const float*)d_in[0];
    const float* k  = (const float*)d_in[1];
    const float* v  = (const float*)d_in[2];
    const float* pd = (const float*)d_in[3];
    float* out = (float*)d_out;

    hash_kernel<<<16384, 256>>>(q, k, pd);
    sort_kernel<<<BH, 128>>>();
    kvprep<<<8192, 256>>>(k, v);
    cudaFuncSetAttribute(attn_kernel, cudaFuncAttributeMaxDynamicSharedMemorySize, SMEMT);
    attn_kernel<<<dim3(32, Hh, Bb), 128, SMEMT>>>(q, out);
}

// round 12
// speedup vs baseline: 1.1116x; 1.0684x over previous
#include <cuda_runtime.h>
#include <cuda_fp16.h>
#include <math.h>
#include <stdint.h>

#define Bb 2
#define Hh 16
#define Nn 2048
#define Dd 128
#define NP 7
#define BH (Bb*Hh)

// ---------------- device scratch ----------------
__device__ int g_qhash[BH*Nn];
__device__ int g_khash[BH*Nn];
__device__ int g_sidx[BH*Nn];
__device__ int g_keep[64];
__device__ __align__(16) unsigned char g_khi[(size_t)BH*Nn*256];
__device__ __align__(16) unsigned char g_vhi[(size_t)BH*Nn*256];

// ---------------- helpers ----------------
__device__ __forceinline__ uint32_t smem_u32(const void* p) {
    uint32_t a;
    asm("{ .reg .u64 t; cvta.to.shared.u64 t, %1; cvt.u32.u64 %0, t; }" : "=r"(a) : "l"(p));
    return a;
}
__device__ __forceinline__ uint32_t pack2h(float a, float b) {
    __half2 h = __floats2half2_rn(a, b);
    return *(uint32_t*)&h;
}
__device__ __forceinline__ void split2h(float x0, float x1, uint32_t& hi, uint32_t& lo) {
    __half h0 = __float2half_rn(x0), h1 = __float2half_rn(x1);
    float r0 = x0 - __half2float(h0), r1 = x1 - __half2float(h1);
    hi = pack2h(__half2float(h0), __half2float(h1));
    lo = pack2h(r0, r1);
}
__device__ __forceinline__ void mma(float d[4], const uint32_t a[4], uint32_t b0, uint32_t b1) {
    asm volatile("mma.sync.aligned.m16n8k16.row.col.f32.f16.f16.f32 "
        "{%0,%1,%2,%3},{%4,%5,%6,%7},{%8,%9},{%0,%1,%2,%3};"
        : "+f"(d[0]), "+f"(d[1]), "+f"(d[2]), "+f"(d[3])
        : "r"(a[0]), "r"(a[1]), "r"(a[2]), "r"(a[3]), "r"(b0), "r"(b1));
}
__device__ __forceinline__ void ldsm4(uint32_t r[4], uint32_t a) {
    asm volatile("ldmatrix.sync.aligned.m8n8.x4.shared.b16 {%0,%1,%2,%3},[%4];"
        : "=r"(r[0]), "=r"(r[1]), "=r"(r[2]), "=r"(r[3]) : "r"(a));
}
__device__ __forceinline__ void ldsm4t(uint32_t r[4], uint32_t a) {
    asm volatile("ldmatrix.sync.aligned.m8n8.x4.trans.shared.b16 {%0,%1,%2,%3},[%4];"
        : "=r"(r[0]), "=r"(r[1]), "=r"(r[2]), "=r"(r[3]) : "r"(a));
}
#define CPA(dst, src) asm volatile("cp.async.cg.shared.global [%0],[%1],16;" :: "r"(dst), "l"(src))
#define CPC()  asm volatile("cp.async.commit_group;" ::: "memory")
#define CPW(n) asm volatile("cp.async.wait_group %0;" :: "n"(n) : "memory")

// ---------------- LSH hash (also zero-inits g_keep) ----------------
__global__ void hash_kernel(const float* __restrict__ q, const float* __restrict__ k,
                            const float* __restrict__ pd) {
    if (blockIdx.x == 0 && threadIdx.x < 64) g_keep[threadIdx.x] = 0;
    __shared__ float pds[Dd*NP];
    for (int i = threadIdx.x; i < Dd*NP; i += blockDim.x) pds[i] = pd[i];
    __syncthreads();
    int warp = threadIdx.x >> 5, lane = threadIdx.x & 31;
    int gid = blockIdx.x * 8 + warp;
    int t = gid >> 16, row = gid & 65535;
    const float* src = t ? k : q;
    int n = row & (Nn-1), h = (row >> 11) & (Hh-1), b = row >> 15;
    float4 x = ((const float4*)(src + ((size_t)(b*Nn+n)*Hh + h)*Dd))[lane];
    int d0 = lane * 4;
    float acc[NP];
    #pragma unroll
    for (int p = 0; p < NP; p++)
        acc[p] = x.x*pds[(d0+0)*NP+p] + x.y*pds[(d0+1)*NP+p]
               + x.z*pds[(d0+2)*NP+p] + x.w*pds[(d0+3)*NP+p];
    #pragma unroll
    for (int p = 0; p < NP; p++)
        #pragma unroll
        for (int o = 16; o; o >>= 1) acc[p] += __shfl_xor_sync(0xffffffffu, acc[p], o);
    if (lane == 0) {
        int bin = 0;
        #pragma unroll
        for (int p = 0; p < NP; p++) bin |= ((acc[p] > 0.f) ? 1 : 0) << p;
        (t ? g_khash : g_qhash)[row] = bin ^ (bin >> 1);
    }
}

// ---------------- stable counting sort per (b,h) + fused keep ----------------
__global__ void sort_kernel() {
    __shared__ int hs[Nn];
    __shared__ int cnt[128];
    __shared__ int ks[64];
    int bh = blockIdx.x, base = bh * Nn;
    for (int i = threadIdx.x; i < Nn; i += 128) hs[i] = g_qhash[base + i];
    if (threadIdx.x < 64) ks[threadIdx.x] = 0;
    __syncthreads();
    int key = threadIdx.x, c = 0;
    for (int i = 0; i < Nn; i++) c += (hs[i] == key);
    cnt[key] = c;
    __syncthreads();
    int off = 0;
    for (int j = 0; j < key; j++) off += cnt[j];
    for (int i = 0; i < Nn; i++)
        if (hs[i] == key) {
            g_sidx[base + off] = i;
            if (key == g_khash[base + off]) ks[off >> 5] = 1;
            off++;
        }
    __syncthreads();
    if (threadIdx.x < 64 && ks[threadIdx.x]) atomicOr(&g_keep[threadIdx.x], 1);
}

// ---------------- K/V prep: single fp16 images ----------------
// K keep-zeroed, V plain. Row images 256B; chunk c stored at (c ^ (n&7)).
__global__ void kvprep(const float* __restrict__ kg, const float* __restrict__ vg) {
    int idx = blockIdx.x * 256 + threadIdx.x;        // 2*BH*Nn*16
    int c = idx & 15;
    int row = (idx >> 4) & (Nn-1);
    int bh  = (idx >> 15) & (BH-1);
    int isv = idx >> 20;
    int h = bh & 15, b = bh >> 4;
    const float* src = isv ? vg : kg;
    float kp = (isv || g_keep[h*4 + (row >> 9)]) ? 1.f : 0.f;
    const float4* sp = (const float4*)(src + ((size_t)(b*Nn+row)*Hh + h)*Dd) + c*2;
    float4 x0 = sp[0], x1 = sp[1];
    uint4 hv;
    hv.x = pack2h(x0.x*kp, x0.y*kp);
    hv.y = pack2h(x0.z*kp, x0.w*kp);
    hv.z = pack2h(x1.x*kp, x1.y*kp);
    hv.w = pack2h(x1.z*kp, x1.w*kp);
    size_t off = ((size_t)(bh*Nn + row))*256 + (size_t)((c ^ (row&7)) << 4);
    *(uint4*)((isv ? g_vhi : g_khi) + off) = hv;
}

// ---------------- HMMA flash attention ----------------
// fp16. S = Qhi*Khi + Qlo*Khi (Q pre-scaled by D^-0.5, exact split;
// K single fp16 -> delta_s ~ 1.8e-4, random across keys). PV = P*V,
// single fp16 P. p = exp(s), no shift. 128-key tiles (two 64-key subs),
// 2-stage cp.async, 64KB/stage.
#define STAGE   65536           /* KHI 32K | V 32K */
#define OFF_V   32768
#define SMEMT   131072

__global__ void __launch_bounds__(256, 1)
attn_kernel(const float* __restrict__ qg, float* __restrict__ out) {
    extern __shared__ __align__(16) unsigned char dsm[];
    uint32_t sb = smem_u32(dsm);
    int tid = threadIdx.x, warp = tid >> 5, lane = tid & 31;
    int qt = 15 - (int)blockIdx.x, h = blockIdx.y, b = blockIdx.z;
    int bh = b*Hh + h;

    // ---- stage Q (gathered rows, pre-scaled, fp16 hi/lo split)
    {
        const float sc = 0.0883883476483184f;   // 128^-0.5
        #pragma unroll
        for (int it = 0; it < 8; it++) {
            int i = tid + it*256;
            int row = i >> 4, c = i & 15;
            int n = g_sidx[bh*Nn + qt*128 + row];
            const float4* qp = (const float4*)(qg + ((size_t)(b*Nn+n)*Hh + h)*Dd) + c*2;
            float4 x0 = qp[0], x1 = qp[1];
            uint4 hv, lv;
            split2h(x0.x*sc, x0.y*sc, hv.x, lv.x);
            split2h(x0.z*sc, x0.w*sc, hv.y, lv.y);
            split2h(x1.x*sc, x1.y*sc, hv.z, lv.z);
            split2h(x1.z*sc, x1.w*sc, hv.w, lv.w);
            uint32_t off = row*256 + ((c ^ (row&7)) << 4);
            *(uint4*)(dsm + off) = hv;
            *(uint4*)(dsm + 32768 + off) = lv;
        }
    }
    __syncthreads();

    // ---- extract Q fragments (A operand, 8 k-steps)
    uint32_t qh[8][4], ql[8][4];
    {
        int qrow = 16*warp + (lane & 15);
        int cbit = lane >> 4, rsw = qrow & 7;
        uint32_t qb = sb + qrow*256;
        #pragma unroll
        for (int kk = 0; kk < 8; kk++) {
            uint32_t a = qb + (((2*kk + cbit) ^ rsw) << 4);
            ldsm4(qh[kk], a);
            ldsm4(ql[kk], a + 32768);
        }
    }
    __syncthreads();

    size_t gbase = (size_t)(bh*Nn) * 256;

    // ---- prologue: stage 0 <- key tile 0 (128 keys: K 32KB, V 32KB)
    #pragma unroll
    for (int i2 = 0; i2 < 8; i2++) {
        int i = tid + i2*256;
        CPA(sb + i*16,         g_khi + gbase + i*16);
        CPA(sb + OFF_V + i*16, g_vhi + gbase + i*16);
    }
    CPC();

    float o[16][4];
    #pragma unroll
    for (int j = 0; j < 16; j++)
        #pragma unroll
        for (int e = 0; e < 4; e++) o[j][e] = 0.f;
    float lA = 0.f, lB = 0.f;

    int keyl = lane & 15, ksw = keyl & 7, cbit = lane >> 4;
    int grA = qt*128 + 16*warp + (lane >> 2), grB = grA + 8;

    for (int kt = 0; kt <= qt; kt++) {
        CPW(0);
        __syncthreads();

        // prefetch next 128-key tile into the other stage
        if (kt < qt) {
            uint32_t st = sb + ((kt+1)&1)*STAGE;
            size_t gs = gbase + (size_t)(kt+1)*32768;
            #pragma unroll
            for (int i2 = 0; i2 < 8; i2++) {
                int i = tid + i2*256;
                CPA(st + i*16,         g_khi + gs + i*16);
                CPA(st + OFF_V + i*16, g_vhi + gs + i*16);
            }
            CPC();
        }

        bool dg = (kt == qt);
        uint32_t stage = sb + (kt&1)*STAGE;

        #pragma unroll
        for (int sub = 0; sub < 2; sub++) {
            uint32_t stK = stage + sub*16384 + keyl*256;
            uint32_t stV = stage + OFF_V + sub*16384 + keyl*256;

            // ---- S = Qhi*Khi + Qlo*Khi  (16x64 per warp)
            float s[8][4];
            #pragma unroll
            for (int j = 0; j < 8; j++)
                #pragma unroll
                for (int e = 0; e < 4; e++) s[j][e] = 0.f;

            #pragma unroll
            for (int kk = 0; kk < 8; kk++) {
                #pragma unroll
                for (int jp = 0; jp < 4; jp++) {
                    uint32_t kb[4];
                    uint32_t a = stK + jp*4096 + (((2*kk + cbit) ^ ksw) << 4);
                    ldsm4(kb, a);
                    mma(s[2*jp],   qh[kk], kb[0], kb[2]);
                    mma(s[2*jp+1], qh[kk], kb[1], kb[3]);
                    mma(s[2*jp],   ql[kk], kb[0], kb[2]);
                    mma(s[2*jp+1], ql[kk], kb[1], kb[3]);
                }
            }

            // ---- softmax: p = exp(s), causal mask on diagonal tile
            float p[8][4];
            #pragma unroll
            for (int j = 0; j < 8; j++) {
                int gc = kt*128 + sub*64 + 8*j + 2*(lane & 3);
                float p0 = __expf(s[j][0]);
                float p1 = __expf(s[j][1]);
                float p2 = __expf(s[j][2]);
                float p3 = __expf(s[j][3]);
                if (dg) {
                    if (gc     > grA) p0 = 0.f;
                    if (gc + 1 > grA) p1 = 0.f;
                    if (gc     > grB) p2 = 0.f;
                    if (gc + 1 > grB) p3 = 0.f;
                }
                lA += p0 + p1;
                lB += p2 + p3;
                p[j][0] = p0; p[j][1] = p1; p[j][2] = p2; p[j][3] = p3;
            }

            // ---- pack P fragments (single fp16)
            uint32_t phi[4][4];
            #pragma unroll
            for (int k2 = 0; k2 < 4; k2++) {
                #pragma unroll
                for (int u = 0; u < 4; u++) {
                    int j = 2*k2 + (u >> 1);
                    phi[k2][u] = pack2h(p[j][(u & 1) ? 2 : 0], p[j][(u & 1) ? 3 : 1]);
                }
            }

            // ---- O += P * V
            #pragma unroll
            for (int k2 = 0; k2 < 4; k2++) {
                #pragma unroll
                for (int jp = 0; jp < 8; jp++) {
                    uint32_t vb[4];
                    uint32_t a = stV + k2*4096 + (((2*jp + cbit) ^ ksw) << 4);
                    ldsm4t(vb, a);
                    mma(o[2*jp],   phi[k2], vb[0], vb[1]);
                    mma(o[2*jp+1], phi[k2], vb[2], vb[3]);
                }
            }
        }
    }

    // ---- epilogue: reduce l, normalize, scatter to original rows
    #pragma unroll
    for (int ox = 1; ox < 4; ox <<= 1) {
        lA += __shfl_xor_sync(0xffffffffu, lA, ox);
        lB += __shfl_xor_sync(0xffffffffu, lB, ox);
    }
    float iA = 1.f / lA, iB = 1.f / lB;
    int nA = g_sidx[bh*Nn + qt*128 + 16*warp + (lane >> 2)];
    int nB = g_sidx[bh*Nn + qt*128 + 16*warp + (lane >> 2) + 8];
    float* opA = out + ((size_t)(b*Nn+nA)*Hh + h)*Dd;
    float* opB = out + ((size_t)(b*Nn+nB)*Hh + h)*Dd;
    #pragma unroll
    for (int j = 0; j < 16; j++) {
        int col = 8*j + 2*(lane & 3);
        *(float2*)(opA + col) = make_float2(o[j][0]*iA, o[j][1]*iA);
        *(float2*)(opB + col) = make_float2(o[j][2]*iB, o[j][3]*iB);
    }
}

// ---------------- launch ----------------
extern "C" void kernel_launch(void* const* d_in, const int* in_sizes, int n_in,
                              void* d_out, int out_size) {
    const float* q  = (const float*)d_in[0];
    const float* k  = (const float*)d_in[1];
    const float* v  = (const float*)d_in[2];
    const float* pd = (const float*)d_in[3];
    float* out = (float*)d_out;

    hash_kernel<<<16384, 256>>>(q, k, pd);
    sort_kernel<<<BH, 128>>>();
    kvprep<<<8192, 256>>>(k, v);
    cudaFuncSetAttribute(attn_kernel, cudaFuncAttributeMaxDynamicSharedMemorySize, SMEMT);
    attn_kernel<<<dim3(16, Hh, Bb), 256, SMEMT>>>(q, out);
}

// round 13
// speedup vs baseline: 1.1633x; 1.0465x over previous
#include <cuda_runtime.h>
#include <cuda_fp16.h>
#include <math.h>
#include <stdint.h>

#define Bb 2
#define Hh 16
#define Nn 2048
#define Dd 128
#define NP 7
#define BH (Bb*Hh)

// ---------------- device scratch ----------------
__device__ int g_qhash[BH*Nn];
__device__ int g_khash[BH*Nn];
__device__ int g_sidx[BH*Nn];
__device__ int g_keep[64];
__device__ __align__(16) unsigned char g_khi[(size_t)BH*Nn*256];
__device__ __align__(16) unsigned char g_vhi[(size_t)BH*Nn*256];

// ---------------- helpers ----------------
__device__ __forceinline__ uint32_t smem_u32(const void* p) {
    uint32_t a;
    asm("{ .reg .u64 t; cvta.to.shared.u64 t, %1; cvt.u32.u64 %0, t; }" : "=r"(a) : "l"(p));
    return a;
}
__device__ __forceinline__ uint32_t pack2h(float a, float b) {
    __half2 h = __floats2half2_rn(a, b);
    return *(uint32_t*)&h;
}
__device__ __forceinline__ void split2h(float x0, float x1, uint32_t& hi, uint32_t& lo) {
    __half h0 = __float2half_rn(x0), h1 = __float2half_rn(x1);
    float r0 = x0 - __half2float(h0), r1 = x1 - __half2float(h1);
    hi = pack2h(__half2float(h0), __half2float(h1));
    lo = pack2h(r0, r1);
}
__device__ __forceinline__ void mma(float d[4], const uint32_t a[4], uint32_t b0, uint32_t b1) {
    asm volatile("mma.sync.aligned.m16n8k16.row.col.f32.f16.f16.f32 "
        "{%0,%1,%2,%3},{%4,%5,%6,%7},{%8,%9},{%0,%1,%2,%3};"
        : "+f"(d[0]), "+f"(d[1]), "+f"(d[2]), "+f"(d[3])
        : "r"(a[0]), "r"(a[1]), "r"(a[2]), "r"(a[3]), "r"(b0), "r"(b1));
}
__device__ __forceinline__ void ldsm4(uint32_t r[4], uint32_t a) {
    asm volatile("ldmatrix.sync.aligned.m8n8.x4.shared.b16 {%0,%1,%2,%3},[%4];"
        : "=r"(r[0]), "=r"(r[1]), "=r"(r[2]), "=r"(r[3]) : "r"(a));
}
__device__ __forceinline__ void ldsm4t(uint32_t r[4], uint32_t a) {
    asm volatile("ldmatrix.sync.aligned.m8n8.x4.trans.shared.b16 {%0,%1,%2,%3},[%4];"
        : "=r"(r[0]), "=r"(r[1]), "=r"(r[2]), "=r"(r[3]) : "r"(a));
}
#define CPA(dst, src) asm volatile("cp.async.cg.shared.global [%0],[%1],16;" :: "r"(dst), "l"(src))
#define CPC()  asm volatile("cp.async.commit_group;" ::: "memory")
#define CPW(n) asm volatile("cp.async.wait_group %0;" :: "n"(n) : "memory")

// ---------------- LSH hash (also zero-inits g_keep) ----------------
__global__ void hash_kernel(const float* __restrict__ q, const float* __restrict__ k,
                            const float* __restrict__ pd) {
    if (blockIdx.x == 0 && threadIdx.x < 64) g_keep[threadIdx.x] = 0;
    __shared__ float pds[Dd*NP];
    for (int i = threadIdx.x; i < Dd*NP; i += blockDim.x) pds[i] = pd[i];
    __syncthreads();
    int warp = threadIdx.x >> 5, lane = threadIdx.x & 31;
    int gid = blockIdx.x * 8 + warp;
    int t = gid >> 16, row = gid & 65535;
    const float* src = t ? k : q;
    int n = row & (Nn-1), h = (row >> 11) & (Hh-1), b = row >> 15;
    float4 x = ((const float4*)(src + ((size_t)(b*Nn+n)*Hh + h)*Dd))[lane];
    int d0 = lane * 4;
    float acc[NP];
    #pragma unroll
    for (int p = 0; p < NP; p++)
        acc[p] = x.x*pds[(d0+0)*NP+p] + x.y*pds[(d0+1)*NP+p]
               + x.z*pds[(d0+2)*NP+p] + x.w*pds[(d0+3)*NP+p];
    #pragma unroll
    for (int p = 0; p < NP; p++)
        #pragma unroll
        for (int o = 16; o; o >>= 1) acc[p] += __shfl_xor_sync(0xffffffffu, acc[p], o);
    if (lane == 0) {
        int bin = 0;
        #pragma unroll
        for (int p = 0; p < NP; p++) bin |= ((acc[p] > 0.f) ? 1 : 0) << p;
        (t ? g_khash : g_qhash)[row] = bin ^ (bin >> 1);
    }
}

// ---------------- stable counting sort per (b,h) + fused keep ----------------
__global__ void sort_kernel() {
    __shared__ int hs[Nn];
    __shared__ int cnt[128];
    __shared__ int ks[64];
    int bh = blockIdx.x, base = bh * Nn;
    for (int i = threadIdx.x; i < Nn; i += 128) hs[i] = g_qhash[base + i];
    if (threadIdx.x < 64) ks[threadIdx.x] = 0;
    __syncthreads();
    int key = threadIdx.x, c = 0;
    for (int i = 0; i < Nn; i++) c += (hs[i] == key);
    cnt[key] = c;
    __syncthreads();
    int off = 0;
    for (int j = 0; j < key; j++) off += cnt[j];
    for (int i = 0; i < Nn; i++)
        if (hs[i] == key) {
            g_sidx[base + off] = i;
            if (key == g_khash[base + off]) ks[off >> 5] = 1;
            off++;
        }
    __syncthreads();
    if (threadIdx.x < 64 && ks[threadIdx.x]) atomicOr(&g_keep[threadIdx.x], 1);
}

// ---------------- K/V prep: single fp16 images ----------------
__global__ void kvprep(const float* __restrict__ kg, const float* __restrict__ vg) {
    int idx = blockIdx.x * 256 + threadIdx.x;        // 2*BH*Nn*16
    int c = idx & 15;
    int row = (idx >> 4) & (Nn-1);
    int bh  = (idx >> 15) & (BH-1);
    int isv = idx >> 20;
    int h = bh & 15, b = bh >> 4;
    const float* src = isv ? vg : kg;
    float kp = (isv || g_keep[h*4 + (row >> 9)]) ? 1.f : 0.f;
    const float4* sp = (const float4*)(src + ((size_t)(b*Nn+row)*Hh + h)*Dd) + c*2;
    float4 x0 = sp[0], x1 = sp[1];
    uint4 hv;
    hv.x = pack2h(x0.x*kp, x0.y*kp);
    hv.y = pack2h(x0.z*kp, x0.w*kp);
    hv.z = pack2h(x1.x*kp, x1.y*kp);
    hv.w = pack2h(x1.z*kp, x1.w*kp);
    size_t off = ((size_t)(bh*Nn + row))*256 + (size_t)((c ^ (row&7)) << 4);
    *(uint4*)((isv ? g_vhi : g_khi) + off) = hv;
}

// ---------------- HMMA flash attention ----------------
// fp16. Q pre-scaled by D^-0.5 * log2(e) -> S is in the log2 domain.
// S = Qhi*K + Qlo*K (exact Q split). p = exp2(s) via ex2.approx.f16x2:
// the packed-half2 exp output IS the P fragment (fuses exp+pack, -75% MUFU)
// and l is summed from the quantized halves (exactly consistent with PV).
// 128-key tiles (two 64-key subs), 2-stage cp.async, 64KB/stage.
#define STAGE   65536           /* KHI 32K | V 32K */
#define OFF_V   32768
#define SMEMT   131072

__global__ void __launch_bounds__(256, 1)
attn_kernel(const float* __restrict__ qg, float* __restrict__ out) {
    extern __shared__ __align__(16) unsigned char dsm[];
    uint32_t sb = smem_u32(dsm);
    int tid = threadIdx.x, warp = tid >> 5, lane = tid & 31;
    int qt = 15 - (int)blockIdx.x, h = blockIdx.y, b = blockIdx.z;
    int bh = b*Hh + h;

    // ---- stage Q (gathered rows, pre-scaled by sc*log2e, fp16 hi/lo split)
    {
        const float sc = 0.12751741f;   // 128^-0.5 * log2(e)
        #pragma unroll
        for (int it = 0; it < 8; it++) {
            int i = tid + it*256;
            int row = i >> 4, c = i & 15;
            int n = g_sidx[bh*Nn + qt*128 + row];
            const float4* qp = (const float4*)(qg + ((size_t)(b*Nn+n)*Hh + h)*Dd) + c*2;
            float4 x0 = qp[0], x1 = qp[1];
            uint4 hv, lv;
            split2h(x0.x*sc, x0.y*sc, hv.x, lv.x);
            split2h(x0.z*sc, x0.w*sc, hv.y, lv.y);
            split2h(x1.x*sc, x1.y*sc, hv.z, lv.z);
            split2h(x1.z*sc, x1.w*sc, hv.w, lv.w);
            uint32_t off = row*256 + ((c ^ (row&7)) << 4);
            *(uint4*)(dsm + off) = hv;
            *(uint4*)(dsm + 32768 + off) = lv;
        }
    }
    __syncthreads();

    // ---- extract Q fragments (A operand, 8 k-steps)
    uint32_t qh[8][4], ql[8][4];
    {
        int qrow = 16*warp + (lane & 15);
        int cbit = lane >> 4, rsw = qrow & 7;
        uint32_t qb = sb + qrow*256;
        #pragma unroll
        for (int kk = 0; kk < 8; kk++) {
            uint32_t a = qb + (((2*kk + cbit) ^ rsw) << 4);
            ldsm4(qh[kk], a);
            ldsm4(ql[kk], a + 32768);
        }
    }
    __syncthreads();

    size_t gbase = (size_t)(bh*Nn) * 256;

    // ---- prologue: stage 0 <- key tile 0 (128 keys: K 32KB, V 32KB)
    #pragma unroll
    for (int i2 = 0; i2 < 8; i2++) {
        int i = tid + i2*256;
        CPA(sb + i*16,         g_khi + gbase + i*16);
        CPA(sb + OFF_V + i*16, g_vhi + gbase + i*16);
    }
    CPC();

    float o[16][4];
    #pragma unroll
    for (int j = 0; j < 16; j++)
        #pragma unroll
        for (int e = 0; e < 4; e++) o[j][e] = 0.f;
    float lA = 0.f, lB = 0.f;

    int keyl = lane & 15, ksw = keyl & 7, cbit = lane >> 4;
    int grA = qt*128 + 16*warp + (lane >> 2), grB = grA + 8;

    for (int kt = 0; kt <= qt; kt++) {
        CPW(0);
        __syncthreads();

        // prefetch next 128-key tile into the other stage
        if (kt < qt) {
            uint32_t st = sb + ((kt+1)&1)*STAGE;
            size_t gs = gbase + (size_t)(kt+1)*32768;
            #pragma unroll
            for (int i2 = 0; i2 < 8; i2++) {
                int i = tid + i2*256;
                CPA(st + i*16,         g_khi + gs + i*16);
                CPA(st + OFF_V + i*16, g_vhi + gs + i*16);
            }
            CPC();
        }

        bool dg = (kt == qt);
        uint32_t stage = sb + (kt&1)*STAGE;

        #pragma unroll
        for (int sub = 0; sub < 2; sub++) {
            uint32_t stK = stage + sub*16384 + keyl*256;
            uint32_t stV = stage + OFF_V + sub*16384 + keyl*256;

            // ---- S = Qhi*K + Qlo*K  (16x64 per warp, log2 domain)
            float s[8][4];
            #pragma unroll
            for (int j = 0; j < 8; j++)
                #pragma unroll
                for (int e = 0; e < 4; e++) s[j][e] = 0.f;

            #pragma unroll
            for (int kk = 0; kk < 8; kk++) {
                #pragma unroll
                for (int jp = 0; jp < 4; jp++) {
                    uint32_t kb[4];
                    uint32_t a = stK + jp*4096 + (((2*kk + cbit) ^ ksw) << 4);
                    ldsm4(kb, a);
                    mma(s[2*jp],   qh[kk], kb[0], kb[2]);
                    mma(s[2*jp+1], qh[kk], kb[1], kb[3]);
                    mma(s[2*jp],   ql[kk], kb[0], kb[2]);
                    mma(s[2*jp+1], ql[kk], kb[1], kb[3]);
                }
            }

            // ---- softmax + pack fused: phi = ex2.approx.f16x2(pack2h(s)),
            //      l accumulated from the quantized halves.
            uint32_t phi[4][4];
            #pragma unroll
            for (int k2 = 0; k2 < 4; k2++) {
                #pragma unroll
                for (int u = 0; u < 4; u++) {
                    int j = 2*k2 + (u >> 1);
                    float a0 = s[j][(u & 1) ? 2 : 0];
                    float a1 = s[j][(u & 1) ? 3 : 1];
                    if (dg) {
                        int gc = kt*128 + sub*64 + 8*j + 2*(lane & 3);
                        int gr = (u & 1) ? grB : grA;
                        if (gc     > gr) a0 = -60000.f;   // exp2 -> 0
                        if (gc + 1 > gr) a1 = -60000.f;
                    }
                    uint32_t hh = pack2h(a0, a1);
                    uint32_t e2;
                    asm("ex2.approx.f16x2 %0, %1;" : "=r"(e2) : "r"(hh));
                    phi[k2][u] = e2;
                    float2 f2 = __half22float2(*(__half2*)&e2);
                    if (u & 1) lB += f2.x + f2.y;
                    else       lA += f2.x + f2.y;
                }
            }

            // ---- O += P * V
            #pragma unroll
            for (int k2 = 0; k2 < 4; k2++) {
                #pragma unroll
                for (int jp = 0; jp < 8; jp++) {
                    uint32_t vb[4];
                    uint32_t a = stV + k2*4096 + (((2*jp + cbit) ^ ksw) << 4);
                    ldsm4t(vb, a);
                    mma(o[2*jp],   phi[k2], vb[0], vb[1]);
                    mma(o[2*jp+1], phi[k2], vb[2], vb[3]);
                }
            }
        }
    }

    // ---- epilogue: reduce l, normalize, scatter to original rows
    #pragma unroll
    for (int ox = 1; ox < 4; ox <<= 1) {
        lA += __shfl_xor_sync(0xffffffffu, lA, ox);
        lB += __shfl_xor_sync(0xffffffffu, lB, ox);
    }
    float iA = 1.f / lA, iB = 1.f / lB;
    int nA = g_sidx[bh*Nn + qt*128 + 16*warp + (lane >> 2)];
    int nB = g_sidx[bh*Nn + qt*128 + 16*warp + (lane >> 2) + 8];
    float* opA = out + ((size_t)(b*Nn+nA)*Hh + h)*Dd;
    float* opB = out + ((size_t)(b*Nn+nB)*Hh + h)*Dd;
    #pragma unroll
    for (int j = 0; j < 16; j++) {
        int col = 8*j + 2*(lane & 3);
        *(float2*)(opA + col) = make_float2(o[j][0]*iA, o[j][1]*iA);
        *(float2*)(opB + col) = make_float2(o[j][2]*iB, o[j][3]*iB);
    }
}

// ---------------- launch ----------------
extern "C" void kernel_launch(void* const* d_in, const int* in_sizes, int n_in,
                              void* d_out, int out_size) {
    const float* q  = (const float*)d_in[0];
    const float* k  = (const float*)d_in[1];
    const float* v  = (const float*)d_in[2];
    const float* pd = (const float*)d_in[3];
    float* out = (float*)d_out;

    hash_kernel<<<16384, 256>>>(q, k, pd);
    sort_kernel<<<BH, 128>>>();
    kvprep<<<8192, 256>>>(k, v);
    cudaFuncSetAttribute(attn_kernel, cudaFuncAttributeMaxDynamicSharedMemorySize, SMEMT);
    attn_kernel<<<dim3(16, Hh, Bb), 256, SMEMT>>>(q, out);
}

// round 14
// speedup vs baseline: 1.3438x; 1.1551x over previous
#include <cuda_runtime.h>
#include <cuda_fp16.h>
#include <math.h>
#include <stdint.h>

#define Bb 2
#define Hh 16
#define Nn 2048
#define Dd 128
#define NP 7
#define BH (Bb*Hh)

// ---------------- device scratch ----------------
__device__ int g_qhash[BH*Nn];
__device__ int g_khash[BH*Nn];
__device__ int g_sidx[BH*Nn];
__device__ int g_keep[64];
__device__ __align__(16) unsigned char g_khi[(size_t)BH*Nn*256];
__device__ __align__(16) unsigned char g_vhi[(size_t)BH*Nn*256];

// ---------------- helpers ----------------
__device__ __forceinline__ uint32_t smem_u32(const void* p) {
    uint32_t a;
    asm("{ .reg .u64 t; cvta.to.shared.u64 t, %1; cvt.u32.u64 %0, t; }" : "=r"(a) : "l"(p));
    return a;
}
__device__ __forceinline__ uint32_t pack2h(float a, float b) {
    __half2 h = __floats2half2_rn(a, b);
    return *(uint32_t*)&h;
}
__device__ __forceinline__ void mma(float d[4], const uint32_t a[4], uint32_t b0, uint32_t b1) {
    asm volatile("mma.sync.aligned.m16n8k16.row.col.f32.f16.f16.f32 "
        "{%0,%1,%2,%3},{%4,%5,%6,%7},{%8,%9},{%0,%1,%2,%3};"
        : "+f"(d[0]), "+f"(d[1]), "+f"(d[2]), "+f"(d[3])
        : "r"(a[0]), "r"(a[1]), "r"(a[2]), "r"(a[3]), "r"(b0), "r"(b1));
}
__device__ __forceinline__ void ldsm4(uint32_t r[4], uint32_t a) {
    asm volatile("ldmatrix.sync.aligned.m8n8.x4.shared.b16 {%0,%1,%2,%3},[%4];"
        : "=r"(r[0]), "=r"(r[1]), "=r"(r[2]), "=r"(r[3]) : "r"(a));
}
__device__ __forceinline__ void ldsm4t(uint32_t r[4], uint32_t a) {
    asm volatile("ldmatrix.sync.aligned.m8n8.x4.trans.shared.b16 {%0,%1,%2,%3},[%4];"
        : "=r"(r[0]), "=r"(r[1]), "=r"(r[2]), "=r"(r[3]) : "r"(a));
}
#define CPA(dst, src) asm volatile("cp.async.cg.shared.global [%0],[%1],16;" :: "r"(dst), "l"(src))
#define CPC()  asm volatile("cp.async.commit_group;" ::: "memory")
#define CPW(n) asm volatile("cp.async.wait_group %0;" :: "n"(n) : "memory")

// ---------------- LSH hash (also zero-inits g_keep) ----------------
__global__ void hash_kernel(const float* __restrict__ q, const float* __restrict__ k,
                            const float* __restrict__ pd) {
    if (blockIdx.x == 0 && threadIdx.x < 64) g_keep[threadIdx.x] = 0;
    __shared__ float pds[Dd*NP];
    for (int i = threadIdx.x; i < Dd*NP; i += blockDim.x) pds[i] = pd[i];
    __syncthreads();
    int warp = threadIdx.x >> 5, lane = threadIdx.x & 31;
    int gid = blockIdx.x * 8 + warp;
    int t = gid >> 16, row = gid & 65535;
    const float* src = t ? k : q;
    int n = row & (Nn-1), h = (row >> 11) & (Hh-1), b = row >> 15;
    float4 x = ((const float4*)(src + ((size_t)(b*Nn+n)*Hh + h)*Dd))[lane];
    int d0 = lane * 4;
    float acc[NP];
    #pragma unroll
    for (int p = 0; p < NP; p++)
        acc[p] = x.x*pds[(d0+0)*NP+p] + x.y*pds[(d0+1)*NP+p]
               + x.z*pds[(d0+2)*NP+p] + x.w*pds[(d0+3)*NP+p];
    #pragma unroll
    for (int p = 0; p < NP; p++)
        #pragma unroll
        for (int o = 16; o; o >>= 1) acc[p] += __shfl_xor_sync(0xffffffffu, acc[p], o);
    if (lane == 0) {
        int bin = 0;
        #pragma unroll
        for (int p = 0; p < NP; p++) bin |= ((acc[p] > 0.f) ? 1 : 0) << p;
        (t ? g_khash : g_qhash)[row] = bin ^ (bin >> 1);
    }
}

// ---------------- stable counting sort per (b,h) + fused keep ----------------
__global__ void sort_kernel() {
    __shared__ int hs[Nn];
    __shared__ int cnt[128];
    __shared__ int ks[64];
    int bh = blockIdx.x, base = bh * Nn;
    for (int i = threadIdx.x; i < Nn; i += 128) hs[i] = g_qhash[base + i];
    if (threadIdx.x < 64) ks[threadIdx.x] = 0;
    __syncthreads();
    int key = threadIdx.x, c = 0;
    for (int i = 0; i < Nn; i++) c += (hs[i] == key);
    cnt[key] = c;
    __syncthreads();
    int off = 0;
    for (int j = 0; j < key; j++) off += cnt[j];
    for (int i = 0; i < Nn; i++)
        if (hs[i] == key) {
            g_sidx[base + off] = i;
            if (key == g_khash[base + off]) ks[off >> 5] = 1;
            off++;
        }
    __syncthreads();
    if (threadIdx.x < 64 && ks[threadIdx.x]) atomicOr(&g_keep[threadIdx.x], 1);
}

// ---------------- K/V prep: single fp16 images ----------------
__global__ void kvprep(const float* __restrict__ kg, const float* __restrict__ vg) {
    int idx = blockIdx.x * 256 + threadIdx.x;        // 2*BH*Nn*16
    int c = idx & 15;
    int row = (idx >> 4) & (Nn-1);
    int bh  = (idx >> 15) & (BH-1);
    int isv = idx >> 20;
    int h = bh & 15, b = bh >> 4;
    const float* src = isv ? vg : kg;
    float kp = (isv || g_keep[h*4 + (row >> 9)]) ? 1.f : 0.f;
    const float4* sp = (const float4*)(src + ((size_t)(b*Nn+row)*Hh + h)*Dd) + c*2;
    float4 x0 = sp[0], x1 = sp[1];
    uint4 hv;
    hv.x = pack2h(x0.x*kp, x0.y*kp);
    hv.y = pack2h(x0.z*kp, x0.w*kp);
    hv.z = pack2h(x1.x*kp, x1.y*kp);
    hv.w = pack2h(x1.z*kp, x1.w*kp);
    size_t off = ((size_t)(bh*Nn + row))*256 + (size_t)((c ^ (row&7)) << 4);
    *(uint4*)((isv ? g_vhi : g_khi) + off) = hv;
}

// ---------------- HMMA flash attention ----------------
// fp16 throughout. Q pre-scaled by D^-0.5*log2(e), SINGLE fp16 Q and K
// (each quant adds ~1.9e-4, budget-checked). S = Q*K (64 MMA/sub).
// p = exp2(s) via ex2.approx.f16x2 (output IS the P fragment).
// l accumulated ON the tensor core: l = P @ ones (4 MMA/sub) -> each
// thread's d[0]/d[2] holds its row's l; bit-consistent with PV.
// 128-key tiles (two 64-key subs), 2-stage cp.async, 64KB/stage.
#define STAGE   65536           /* KHI 32K | V 32K */
#define OFF_V   32768
#define SMEMT   131072
#define ONES2   0x3C003C00u     /* fp16x2 {1,1} */

__global__ void __launch_bounds__(256, 1)
attn_kernel(const float* __restrict__ qg, float* __restrict__ out) {
    extern __shared__ __align__(16) unsigned char dsm[];
    uint32_t sb = smem_u32(dsm);
    int tid = threadIdx.x, warp = tid >> 5, lane = tid & 31;
    int qt = 15 - (int)blockIdx.x, h = blockIdx.y, b = blockIdx.z;
    int bh = b*Hh + h;

    // ---- stage Q (gathered rows, pre-scaled by sc*log2e, single fp16)
    {
        const float sc = 0.12751741f;   // 128^-0.5 * log2(e)
        #pragma unroll
        for (int it = 0; it < 8; it++) {
            int i = tid + it*256;
            int row = i >> 4, c = i & 15;
            int n = g_sidx[bh*Nn + qt*128 + row];
            const float4* qp = (const float4*)(qg + ((size_t)(b*Nn+n)*Hh + h)*Dd) + c*2;
            float4 x0 = qp[0], x1 = qp[1];
            uint4 hv;
            hv.x = pack2h(x0.x*sc, x0.y*sc);
            hv.y = pack2h(x0.z*sc, x0.w*sc);
            hv.z = pack2h(x1.x*sc, x1.y*sc);
            hv.w = pack2h(x1.z*sc, x1.w*sc);
            *(uint4*)(dsm + row*256 + ((c ^ (row&7)) << 4)) = hv;
        }
    }
    __syncthreads();

    // ---- extract Q fragments (A operand, 8 k-steps)
    uint32_t qh[8][4];
    {
        int qrow = 16*warp + (lane & 15);
        int cbit = lane >> 4, rsw = qrow & 7;
        uint32_t qb = sb + qrow*256;
        #pragma unroll
        for (int kk = 0; kk < 8; kk++)
            ldsm4(qh[kk], qb + (((2*kk + cbit) ^ rsw) << 4));
    }
    __syncthreads();

    size_t gbase = (size_t)(bh*Nn) * 256;

    // ---- prologue: stage 0 <- key tile 0 (128 keys: K 32KB, V 32KB)
    #pragma unroll
    for (int i2 = 0; i2 < 8; i2++) {
        int i = tid + i2*256;
        CPA(sb + i*16,         g_khi + gbase + i*16);
        CPA(sb + OFF_V + i*16, g_vhi + gbase + i*16);
    }
    CPC();

    float o[16][4];
    #pragma unroll
    for (int j = 0; j < 16; j++)
        #pragma unroll
        for (int e = 0; e < 4; e++) o[j][e] = 0.f;
    float lfr[4] = {0.f, 0.f, 0.f, 0.f};   // l = P @ ones (tensor-core)

    int keyl = lane & 15, ksw = keyl & 7, cbit = lane >> 4;
    int grA = qt*128 + 16*warp + (lane >> 2), grB = grA + 8;

    for (int kt = 0; kt <= qt; kt++) {
        CPW(0);
        __syncthreads();

        // prefetch next 128-key tile into the other stage
        if (kt < qt) {
            uint32_t st = sb + ((kt+1)&1)*STAGE;
            size_t gs = gbase + (size_t)(kt+1)*32768;
            #pragma unroll
            for (int i2 = 0; i2 < 8; i2++) {
                int i = tid + i2*256;
                CPA(st + i*16,         g_khi + gs + i*16);
                CPA(st + OFF_V + i*16, g_vhi + gs + i*16);
            }
            CPC();
        }

        bool dg = (kt == qt);
        uint32_t stage = sb + (kt&1)*STAGE;

        #pragma unroll
        for (int sub = 0; sub < 2; sub++) {
            uint32_t stK = stage + sub*16384 + keyl*256;
            uint32_t stV = stage + OFF_V + sub*16384 + keyl*256;

            // ---- S = Q * K  (16x64 per warp, log2 domain)
            float s[8][4];
            #pragma unroll
            for (int j = 0; j < 8; j++)
                #pragma unroll
                for (int e = 0; e < 4; e++) s[j][e] = 0.f;

            #pragma unroll
            for (int kk = 0; kk < 8; kk++) {
                #pragma unroll
                for (int jp = 0; jp < 4; jp++) {
                    uint32_t kb[4];
                    ldsm4(kb, stK + jp*4096 + (((2*kk + cbit) ^ ksw) << 4));
                    mma(s[2*jp],   qh[kk], kb[0], kb[2]);
                    mma(s[2*jp+1], qh[kk], kb[1], kb[3]);
                }
            }

            // ---- softmax+pack fused: phi = ex2.approx.f16x2(pack2h(s))
            uint32_t phi[4][4];
            #pragma unroll
            for (int k2 = 0; k2 < 4; k2++) {
                #pragma unroll
                for (int u = 0; u < 4; u++) {
                    int j = 2*k2 + (u >> 1);
                    float a0 = s[j][(u & 1) ? 2 : 0];
                    float a1 = s[j][(u & 1) ? 3 : 1];
                    if (dg) {
                        int gc = kt*128 + sub*64 + 8*j + 2*(lane & 3);
                        int gr = (u & 1) ? grB : grA;
                        if (gc     > gr) a0 = -60000.f;   // exp2 -> 0
                        if (gc + 1 > gr) a1 = -60000.f;
                    }
                    uint32_t hh = pack2h(a0, a1);
                    asm("ex2.approx.f16x2 %0, %1;" : "=r"(phi[k2][u]) : "r"(hh));
                }
            }

            // ---- l += P @ ones ; O += P * V
            #pragma unroll
            for (int k2 = 0; k2 < 4; k2++) {
                mma(lfr, phi[k2], ONES2, ONES2);
                #pragma unroll
                for (int jp = 0; jp < 8; jp++) {
                    uint32_t vb[4];
                    ldsm4t(vb, stV + k2*4096 + (((2*jp + cbit) ^ ksw) << 4));
                    mma(o[2*jp],   phi[k2], vb[0], vb[1]);
                    mma(o[2*jp+1], phi[k2], vb[2], vb[3]);
                }
            }
        }
    }

    // ---- epilogue: normalize (l already per-row in lfr), scatter
    float iA = 1.f / lfr[0], iB = 1.f / lfr[2];
    int nA = g_sidx[bh*Nn + qt*128 + 16*warp + (lane >> 2)];
    int nB = g_sidx[bh*Nn + qt*128 + 16*warp + (lane >> 2) + 8];
    float* opA = out + ((size_t)(b*Nn+nA)*Hh + h)*Dd;
    float* opB = out + ((size_t)(b*Nn+nB)*Hh + h)*Dd;
    #pragma unroll
    for (int j = 0; j < 16; j++) {
        int col = 8*j + 2*(lane & 3);
        *(float2*)(opA + col) = make_float2(o[j][0]*iA, o[j][1]*iA);
        *(float2*)(opB + col) = make_float2(o[j][2]*iB, o[j][3]*iB);
    }
}

// ---------------- launch ----------------
extern "C" void kernel_launch(void* const* d_in, const int* in_sizes, int n_in,
                              void* d_out, int out_size) {
    const float* q  = (const float*)d_in[0];
    const float* k  = (const float*)d_in[1];
    const float* v  = (const float*)d_in[2];
    const float* pd = (const float*)d_in[3];
    float* out = (float*)d_out;

    hash_kernel<<<16384, 256>>>(q, k, pd);
    sort_kernel<<<BH, 128>>>();
    kvprep<<<8192, 256>>>(k, v);
    cudaFuncSetAttribute(attn_kernel, cudaFuncAttributeMaxDynamicSharedMemorySize, SMEMT);
    attn_kernel<<<dim3(16, Hh, Bb), 256, SMEMT>>>(q, out);
}